// round 5
// baseline (speedup 1.0000x reference)
#include <cuda_runtime.h>
#include <cuda_fp16.h>

// Problem constants (fixed shapes from the reference)
#define NE      513              // NUM_EDGES + 1
#define LHOPS   5
#define HEADS   8
#define FEAT    64
#define NPAIRS  (8*128*128)      // 131072
#define TBL     (LHOPS*NE*HEADS) // 20520 halves = 41040 B
#define GRID    296
#define CHUNK   443              // ceil(NPAIRS / 296)

// Dynamic smem partition (bytes)
#define OFF_TBL 0
#define OFF_IDX 41040                   // 10*CHUNK ints = 17720 B
#define OFF_SC  (41040 + 17728)         // CHUNK floats = 1772 B (idx padded to 16B)
#define SMEM_TOTAL (OFF_SC + 1792)      // 60560 B per CTA

// Precomputed projection table proj[l][e][h] in fp16
__device__ __align__(16) __half g_proj[TBL];

// Kernel A (tiled mini-GEMM): proj[l][e][h] = sum_f edge_emb[e][f]*attn_w[l][f][h]
// grid = (17 e-tiles, 5 l), block = 256 = 32 e x 8 h. w[l] staged in smem.
__global__ void proj_kernel(const float* __restrict__ emb,
                            const float* __restrict__ w) {
    __shared__ __align__(16) float s_w[FEAT * HEADS];   // 2 KB
    const int l   = blockIdx.y;
    const int tid = threadIdx.x;
    for (int i = tid; i < FEAT * HEADS / 4; i += 256)
        ((float4*)s_w)[i] = ((const float4*)(w + l * FEAT * HEADS))[i];
    __syncthreads();

    const int e = blockIdx.x * 32 + (tid >> 3);
    const int h = tid & 7;
    if (e < NE) {
        const float* er = emb + e * FEAT;
        float acc = 0.f;
        #pragma unroll
        for (int f = 0; f < FEAT; ++f)
            acc = fmaf(er[f], s_w[f * HEADS + h], acc);   // broadcast, conflict-free
        g_proj[(l * NE + e) * HEADS + h] = __float2half(acc);
    }
#if __CUDA_ARCH__ >= 900
    cudaTriggerProgrammaticLaunchCompletion();
#endif
}

// Kernel B: 296 CTAs (2/SM) x 1024 threads, PDL secondary.
// Phase 0 (overlaps proj via PDL): load pd indices + dist scales into smem.
// Phase 1 (after griddepsync): stage fp16 table into smem.
// Phase 2: gather — one LDS.128 per (pair,hop) = all 8 heads, fp32 accumulate.
__global__ void __launch_bounds__(1024, 2)
enc_kernel(const void* __restrict__ distp,
           const void* __restrict__ pdp,
           float* __restrict__ out) {
    extern __shared__ __align__(16) char sm[];
    __half* s_tbl = (__half*)(sm + OFF_TBL);
    int*    s_idx = (int*)  (sm + OFF_IDX);
    float*  s_sc  = (float*)(sm + OFF_SC);

    const int tid   = threadIdx.x;
    const int base  = blockIdx.x * CHUNK;
    const int npair = min(CHUNK, NPAIRS - base);

    // dtype detection: dist in [1,5]; int64 (LE) => word #1 is high half == 0.
    const bool is64 = (((const int*)distp)[1] == 0);

    // ---- Phase 0: pd + dist -> smem (independent of proj; overlaps it) ----
    if (is64) {
        // pair = 10 int64 = 5 int4; int4 #q holds hops j=2q (.x) and 2q+1 (.z)
        const int4* p = (const int4*)pdp + (size_t)base * 5;
        for (int k = tid; k < npair * 5; k += 1024) {
            int4 v = p[k];
            int pr = k / 5, q = k - 5 * (k / 5);
            s_idx[(2 * q)     * CHUNK + pr] = v.x;
            s_idx[(2 * q + 1) * CHUNK + pr] = v.z;
        }
        if (tid < npair)
            s_sc[tid] = 0.5f / (float)((const int*)distp)[2 * (base + tid)];
    } else {
        // pair = 10 int32 = 5 int2
        const int2* p = (const int2*)pdp + (size_t)base * 5;
        for (int k = tid; k < npair * 5; k += 1024) {
            int2 v = p[k];
            int pr = k / 5, q = k - 5 * (k / 5);
            s_idx[(2 * q)     * CHUNK + pr] = v.x;
            s_idx[(2 * q + 1) * CHUNK + pr] = v.y;
        }
        if (tid < npair)
            s_sc[tid] = 0.5f / (float)((const int*)distp)[base + tid];
    }

#if __CUDA_ARCH__ >= 900
    cudaGridDependencySynchronize();   // wait for proj's g_proj writes
#endif

    // ---- Phase 1: stage fp16 table (41040 B = 2565 x 16B) ----
    {
        const float4* gsrc = (const float4*)g_proj;
        float4* sdst = (float4*)s_tbl;
        #pragma unroll
        for (int r = 0; r < 3; ++r) {
            int i = tid + r * 1024;
            if (i < TBL / 8) sdst[i] = gsrc[i];
        }
    }
    __syncthreads();

    // ---- Phase 2: gather ----
    if (tid < npair) {
        const float sc = s_sc[tid];
        float4 al = make_float4(0.f, 0.f, 0.f, 0.f);
        float4 ah = al;
        #pragma unroll
        for (int j = 0; j < 2 * LHOPS; ++j) {
            const int l   = j >> 1;
            const int idx = s_idx[j * CHUNK + tid];     // conflict-free
            float4 rv = *(const float4*)(s_tbl + (l * NE + idx) * HEADS);
            float2 f0 = __half22float2(*(__half2*)&rv.x);
            float2 f1 = __half22float2(*(__half2*)&rv.y);
            float2 f2 = __half22float2(*(__half2*)&rv.z);
            float2 f3 = __half22float2(*(__half2*)&rv.w);
            al.x += f0.x; al.y += f0.y; al.z += f1.x; al.w += f1.y;
            ah.x += f2.x; ah.y += f2.y; ah.z += f3.x; ah.w += f3.y;
        }
        float4* o = (float4*)(out + (size_t)(base + tid) * HEADS);
        o[0] = make_float4(al.x * sc, al.y * sc, al.z * sc, al.w * sc);
        o[1] = make_float4(ah.x * sc, ah.y * sc, ah.z * sc, ah.w * sc);
    }
}

extern "C" void kernel_launch(void* const* d_in, const int* in_sizes, int n_in,
                              void* d_out, int out_size) {
    const void*  dist = d_in[0];
    const void*  pd   = d_in[1];
    const float* emb  = (const float*)d_in[2];
    const float* w    = (const float*)d_in[3];

    // dynamic smem opt-in (idempotent, unconditional)
    cudaFuncSetAttribute(enc_kernel,
                         cudaFuncAttributeMaxDynamicSharedMemorySize,
                         SMEM_TOTAL);

    proj_kernel<<<dim3((NE + 31) / 32, LHOPS), 256>>>(emb, w);

    // PDL secondary: may start during proj; griddepsync guards g_proj reads.
    cudaLaunchConfig_t cfg = {};
    cfg.gridDim  = dim3(GRID);
    cfg.blockDim = dim3(1024);
    cfg.dynamicSmemBytes = SMEM_TOTAL;
    cfg.stream = 0;
    cudaLaunchAttribute attr[1];
    attr[0].id = cudaLaunchAttributeProgrammaticStreamSerialization;
    attr[0].val.programmaticStreamSerializationAllowed = 1;
    cfg.attrs = attr;
    cfg.numAttrs = 1;
    cudaLaunchKernelEx(&cfg, enc_kernel, dist, pd, (float*)d_out);
}

// round 6
// speedup vs baseline: 1.1548x; 1.1548x over previous
#include <cuda_runtime.h>
#include <cuda_fp16.h>

// Problem constants (fixed shapes from the reference)
#define NE      513              // NUM_EDGES + 1
#define LHOPS   5
#define HEADS   8
#define FEAT    64
#define NPAIRS  (8*128*128)      // 131072
#define TBL     (LHOPS*NE*HEADS) // 20520 halves = 41040 B
#define GRID    148
#define CHUNK   886              // ceil(NPAIRS / 148)

// Precomputed projection table proj[l][e][h] in fp16
__device__ __align__(16) __half g_proj[TBL];

// Kernel A (tiled mini-GEMM): proj[l][e][h] = sum_f edge_emb[e][f]*attn_w[l][f][h]
// grid = (17 e-tiles, 5 l), block = 256 = 32 e x 8 h. w[l] staged in smem.
__global__ void proj_kernel(const float* __restrict__ emb,
                            const float* __restrict__ w) {
    __shared__ __align__(16) float s_w[FEAT * HEADS];   // 2 KB
    const int l   = blockIdx.y;
    const int tid = threadIdx.x;
    for (int i = tid; i < FEAT * HEADS / 4; i += 256)
        ((float4*)s_w)[i] = ((const float4*)(w + l * FEAT * HEADS))[i];
    __syncthreads();

    const int e = blockIdx.x * 32 + (tid >> 3);
    const int h = tid & 7;
    if (e < NE) {
        const float* er = emb + e * FEAT;
        float acc = 0.f;
        #pragma unroll
        for (int f = 0; f < FEAT; ++f)
            acc = fmaf(er[f], s_w[f * HEADS + h], acc);   // broadcast, conflict-free
        g_proj[(l * NE + e) * HEADS + h] = __float2half(acc);
    }
#if __CUDA_ARCH__ >= 900
    cudaTriggerProgrammaticLaunchCompletion();
#endif
}

// Kernel B: 148 CTAs (1/SM) x 1024 threads. Table staged ONCE per SM.
// Order: pd/dist register loads FIRST (latency overlaps staging), then
// cooperative table staging, sync, then gather with pairwise-HADD2 reduce.
__global__ void __launch_bounds__(1024, 1)
enc_kernel(const void* __restrict__ distp,
           const void* __restrict__ pdp,
           float* __restrict__ out) {
    __shared__ __align__(16) __half s_tbl[TBL];  // 41040 B static
    const int tid  = threadIdx.x;
    const int pair = blockIdx.x * CHUNK + tid;
    const bool act = (tid < CHUNK) && (pair < NPAIRS);
    const int p    = act ? pair : blockIdx.x * CHUNK;  // clamp: loads unconditional

    // dtype detection: dist in [1,5]; int64 (LE) => word #1 is high half == 0.
    const bool is64 = (((const int*)distp)[1] == 0);

    // ---- Phase 0: pd + dist loads into registers (overlap with staging) ----
    int idx[2 * LHOPS];
    float scale;
    if (is64) {
        // 10 int64 = 80 B contiguous, 16B-aligned
        const int4* pp = (const int4*)((const long long*)pdp + (size_t)p * 10);
        #pragma unroll
        for (int j = 0; j < 5; ++j) {
            int4 v = pp[j];              // low words of two int64: .x, .z
            idx[2 * j]     = v.x;
            idx[2 * j + 1] = v.z;
        }
        scale = 0.5f / (float)((const int*)distp)[2 * p];  // low word
    } else {
        // 10 int32 = 40 B contiguous, 8B-aligned
        const int2* pp = (const int2*)((const int*)pdp + (size_t)p * 10);
        #pragma unroll
        for (int j = 0; j < 5; ++j) {
            int2 v = pp[j];
            idx[2 * j]     = v.x;
            idx[2 * j + 1] = v.y;
        }
        scale = 0.5f / (float)((const int*)distp)[p];
    }

#if __CUDA_ARCH__ >= 900
    cudaGridDependencySynchronize();   // g_proj ready (PDL)
#endif

    // ---- Phase 1: stage fp16 table (41040 B = 2565 x 16B) ----
    {
        const float4* gsrc = (const float4*)g_proj;
        float4* sdst = (float4*)s_tbl;
        #pragma unroll
        for (int r = 0; r < 3; ++r) {
            int i = tid + r * 1024;
            if (i < TBL / 8) sdst[i] = gsrc[i];
        }
    }
    __syncthreads();

    // ---- Phase 2: gather. Hops 2q,2q+1 share level q: pairwise HADD2 first,
    // then fp32 accumulate (one fp16 add of 2 terms: negligible error).
    if (act) {
        float4 al = make_float4(0.f, 0.f, 0.f, 0.f);
        float4 ah = al;
        #pragma unroll
        for (int q = 0; q < LHOPS; ++q) {
            const __half* base = s_tbl + q * NE * HEADS;
            float4 v0 = *(const float4*)(base + idx[2 * q]     * HEADS);
            float4 v1 = *(const float4*)(base + idx[2 * q + 1] * HEADS);
            __half2 s0 = __hadd2(*(__half2*)&v0.x, *(__half2*)&v1.x);
            __half2 s1 = __hadd2(*(__half2*)&v0.y, *(__half2*)&v1.y);
            __half2 s2 = __hadd2(*(__half2*)&v0.z, *(__half2*)&v1.z);
            __half2 s3 = __hadd2(*(__half2*)&v0.w, *(__half2*)&v1.w);
            float2 f0 = __half22float2(s0);
            float2 f1 = __half22float2(s1);
            float2 f2 = __half22float2(s2);
            float2 f3 = __half22float2(s3);
            al.x += f0.x; al.y += f0.y; al.z += f1.x; al.w += f1.y;
            ah.x += f2.x; ah.y += f2.y; ah.z += f3.x; ah.w += f3.y;
        }
        float4* o = (float4*)(out + (size_t)p * HEADS);
        o[0] = make_float4(al.x * scale, al.y * scale, al.z * scale, al.w * scale);
        o[1] = make_float4(ah.x * scale, ah.y * scale, ah.z * scale, ah.w * scale);
    }
}

extern "C" void kernel_launch(void* const* d_in, const int* in_sizes, int n_in,
                              void* d_out, int out_size) {
    const void*  dist = d_in[0];
    const void*  pd   = d_in[1];
    const float* emb  = (const float*)d_in[2];
    const float* w    = (const float*)d_in[3];

    proj_kernel<<<dim3((NE + 31) / 32, LHOPS), 256>>>(emb, w);

    // PDL secondary: may start during proj; griddepsync guards g_proj reads.
    cudaLaunchConfig_t cfg = {};
    cfg.gridDim  = dim3(GRID);
    cfg.blockDim = dim3(1024);
    cfg.dynamicSmemBytes = 0;
    cfg.stream = 0;
    cudaLaunchAttribute attr[1];
    attr[0].id = cudaLaunchAttributeProgrammaticStreamSerialization;
    attr[0].val.programmaticStreamSerializationAllowed = 1;
    cfg.attrs = attr;
    cfg.numAttrs = 1;
    cudaLaunchKernelEx(&cfg, enc_kernel, dist, pd, (float*)d_out);
}